// round 5
// baseline (speedup 1.0000x reference)
#include <cuda_runtime.h>
#include <math.h>

#define BN 1024
#define DN 128
#define HN 128
#define LN_EPS 1e-5f

__device__ float g_dm[BN * DN];

typedef unsigned long long ull;
typedef unsigned int uint;

// ===========================================================================
// order-preserving float <-> uint encode
// ===========================================================================
__device__ __forceinline__ uint encf(float f) {
    uint u = __float_as_uint(f);
    return u ^ ((u & 0x80000000u) ? 0xFFFFFFFFu : 0x80000000u);
}
__device__ __forceinline__ float decf(uint u) {
    u ^= (u & 0x80000000u) ? 0x80000000u : 0xFFFFFFFFu;
    return __uint_as_float(u);
}

// ===========================================================================
// K1: per-column mean |x_i - x_j| via hybrid bitonic sort.
// 128 blocks, 512 threads, 2 keys/thread (positions 64w+lane, +32).
// Phase-B smem stages fully unrolled; syncs are named barriers scoped to
// the exact dependent thread group (bitonic blocks nest, groups align).
// ===========================================================================
__device__ __forceinline__ void g64(int t) {
    asm volatile("bar.sync %0, 64;"  :: "r"(1 + (t >> 6)) : "memory");
}
__device__ __forceinline__ void g128(int t) {
    asm volatile("bar.sync %0, 128;" :: "r"(9 + (t >> 7)) : "memory");
}
__device__ __forceinline__ void g256(int t) {
    asm volatile("bar.sync %0, 256;" :: "r"(13 + (t >> 8)) : "memory");
}

template<int K, int J>
__device__ __forceinline__ void sstage(uint* __restrict__ sv, int t) {
    int i = ((t & ~(J - 1)) << 1) | (t & (J - 1));
    int ixj = i | J;
    uint a = sv[i];
    uint b = sv[ixj];
    if ((a > b) == ((i & K) == 0)) { sv[i] = b; sv[ixj] = a; }
}

// register tail: j = 32 (pair) then j = 16..1 via shfl. up uniform per thread.
__device__ __forceinline__ void rtail(uint& r0, uint& r1, int p0, bool up) {
    uint lo = min(r0, r1), hi = max(r0, r1);
    r0 = up ? lo : hi;
    r1 = up ? hi : lo;
    #pragma unroll
    for (int j = 16; j > 0; j >>= 1) {
        bool km = (((p0 & j) == 0) == up);
        uint o0 = __shfl_xor_sync(0xffffffffu, r0, j);
        r0 = km ? min(r0, o0) : max(r0, o0);
        uint o1 = __shfl_xor_sync(0xffffffffu, r1, j);
        r1 = km ? min(r1, o1) : max(r1, o1);
    }
}

__global__ __launch_bounds__(512) void col_absdiff_mean_kernel(
    const float* __restrict__ x, float* __restrict__ dm)
{
    __shared__ uint  sv[BN];
    __shared__ float ps[BN];
    __shared__ float wsum[16];

    const int d = blockIdx.x;
    const int t = threadIdx.x;
    const int lane = t & 31;
    const int w = t >> 5;
    const int p0 = (w << 6) + lane;
    const int p1 = p0 + 32;

    const float f0 = x[p0 * DN + d];
    const float f1 = x[p1 * DN + d];
    const uint e0 = encf(f0);
    const uint e1 = encf(f1);
    uint r0 = e0, r1 = e1;

    // ---- phase A: k = 2..64, registers/shfl only ----
    #pragma unroll
    for (int k = 2; k <= 64; k <<= 1) {
        #pragma unroll
        for (int j = k >> 1; j > 0; j >>= 1) {
            if (j == 32) {
                bool up = ((p0 & k) == 0);
                uint lo = min(r0, r1), hi = max(r0, r1);
                r0 = up ? lo : hi;
                r1 = up ? hi : lo;
            } else {
                bool up0 = ((p0 & k) == 0);
                bool km0 = (((p0 & j) == 0) == up0);
                uint o0 = __shfl_xor_sync(0xffffffffu, r0, j);
                r0 = km0 ? min(r0, o0) : max(r0, o0);
                bool up1 = ((p1 & k) == 0);
                bool km1 = (((p1 & j) == 0) == up1);
                uint o1 = __shfl_xor_sync(0xffffffffu, r1, j);
                r1 = km1 ? min(r1, o1) : max(r1, o1);
            }
        }
    }

    // ---- phase B: unrolled smem stages + grouped named barriers ----
    // K = 128
    sv[p0] = r0; sv[p1] = r1;
    g64(t);
    sstage<128, 64>(sv, t);
    g64(t);
    r0 = sv[p0]; r1 = sv[p1];
    rtail(r0, r1, p0, (p0 & 128) == 0);

    // K = 256
    sv[p0] = r0; sv[p1] = r1;
    g128(t);
    sstage<256, 128>(sv, t);
    g128(t);
    sstage<256, 64>(sv, t);
    g64(t);
    r0 = sv[p0]; r1 = sv[p1];
    rtail(r0, r1, p0, (p0 & 256) == 0);

    // K = 512
    sv[p0] = r0; sv[p1] = r1;
    g256(t);
    sstage<512, 256>(sv, t);
    g256(t);
    sstage<512, 128>(sv, t);
    g128(t);
    sstage<512, 64>(sv, t);
    g64(t);
    r0 = sv[p0]; r1 = sv[p1];
    rtail(r0, r1, p0, (p0 & 512) == 0);

    // K = 1024
    sv[p0] = r0; sv[p1] = r1;
    __syncthreads();
    sstage<1024, 512>(sv, t);
    __syncthreads();
    sstage<1024, 256>(sv, t);
    g256(t);
    sstage<1024, 128>(sv, t);
    g128(t);
    sstage<1024, 64>(sv, t);
    g64(t);
    r0 = sv[p0]; r1 = sv[p1];
    rtail(r0, r1, p0, true);

    // ---- store sorted keys + prefix sums ----
    sv[p0] = r0;
    sv[p1] = r1;
    float v0 = decf(r0);
    float v1 = decf(r1);

    float s0 = v0;
    #pragma unroll
    for (int o = 1; o < 32; o <<= 1) {
        float n = __shfl_up_sync(0xffffffffu, s0, o);
        if (lane >= o) s0 += n;
    }
    float T0 = __shfl_sync(0xffffffffu, s0, 31);
    float s1 = v1;
    #pragma unroll
    for (int o = 1; o < 32; o <<= 1) {
        float n = __shfl_up_sync(0xffffffffu, s1, o);
        if (lane >= o) s1 += n;
    }
    float T1 = __shfl_sync(0xffffffffu, s1, 31);
    if (lane == 0) wsum[w] = T0 + T1;
    __syncthreads();
    if (t < 16) {
        float v = wsum[t];
        #pragma unroll
        for (int o = 1; o < 16; o <<= 1) {
            float n = __shfl_up_sync(0x0000ffffu, v, o);
            if (t >= o) v += n;
        }
        wsum[t] = v;
    }
    __syncthreads();
    const float S = wsum[15];
    const float wexcl = (w == 0) ? 0.0f : wsum[w - 1];
    ps[p0] = wexcl + s0;
    ps[p1] = wexcl + T0 + s1;
    __syncthreads();

    // ---- binary-search rank of original elements; closed-form write ----
    {
        int q = 0;
        #pragma unroll
        for (int st = 512; st > 0; st >>= 1) {
            int nq = q + st;
            if (sv[nq - 1] < e0) q = nq;
        }
        float o = f0 * (float)(2 * (q + 1) - BN) + S - 2.0f * ps[q];
        dm[p0 * DN + d] = o * (1.0f / (float)BN);
    }
    {
        int q = 0;
        #pragma unroll
        for (int st = 512; st > 0; st >>= 1) {
            int nq = q + st;
            if (sv[nq - 1] < e1) q = nq;
        }
        float o = f1 * (float)(2 * (q + 1) - BN) + S - 2.0f * ps[q];
        dm[p1 * DN + d] = o * (1.0f / (float)BN);
    }
}

// ===========================================================================
// K3: fused tail. 128 blocks x 8 rows, 1024 threads (32 warps, occ 50%).
// Warp = col-group of 4 cols (col = 4*warp + (lane>>3)&3 at epilogue);
// lane = k-chunk of 4 k's. Weights direct LDG.128 (L2, exact bytes).
// Butterfly over 32 lanes: payload 16 ull -> 1 float (col, row = lane&7).
// ===========================================================================
__device__ __forceinline__ ull fma2(ull a, ull b, ull c) {
    ull d;
    asm("fma.rn.f32x2 %0, %1, %2, %3;" : "=l"(d) : "l"(a), "l"(b), "l"(c));
    return d;
}
__device__ __forceinline__ ull add2(ull a, ull b) {
    ull d;
    asm("add.rn.f32x2 %0, %1, %2;" : "=l"(d) : "l"(a), "l"(b));
    return d;
}
__device__ __forceinline__ ull dup2(float w) {
    ull d;
    asm("mov.b64 %0, {%1, %1};" : "=l"(d) : "r"(__float_as_uint(w)));
    return d;
}

#define CW 36   /* floats per 4-k chunk: 4k*8r = 32 data + 4 pad */
#define IDX(k, r) ((((k) >> 2) * CW) + (((k) & 3) << 3) + (r))

__device__ __forceinline__ void load_w(const float* __restrict__ W,
                                       int colbase, int k0, float4 wv[4])
{
    #pragma unroll
    for (int c = 0; c < 4; c++)
        wv[c] = *(const float4*)(W + (colbase + c) * DN + k0);
}

__device__ __forceinline__ void mv_acc(const float* __restrict__ ip,
                                       const float4 wv[4], ull A[16])
{
    #pragma unroll
    for (int kl = 0; kl < 4; kl++) {
        ulonglong2 q0 = *(const ulonglong2*)(ip + kl * 8);       // rows 0-3
        ulonglong2 q1 = *(const ulonglong2*)(ip + kl * 8 + 4);   // rows 4-7
        #pragma unroll
        for (int c = 0; c < 4; c++) {
            ull w2 = dup2(((const float*)&wv[c])[kl]);
            A[c * 4 + 0] = fma2(q0.x, w2, A[c * 4 + 0]);
            A[c * 4 + 1] = fma2(q0.y, w2, A[c * 4 + 1]);
            A[c * 4 + 2] = fma2(q1.x, w2, A[c * 4 + 2]);
            A[c * 4 + 3] = fma2(q1.y, w2, A[c * 4 + 3]);
        }
    }
}

// 5-stage recursive-halving butterfly over 32 lanes.
// lane m ends with the scalar for (col = (m>>3)&3 of group, row = m&7).
__device__ __forceinline__ float butterfly32(ull A[16], int m)
{
    #pragma unroll
    for (int j = 0; j < 8; j++) {
        ull snd = (m & 16) ? A[j] : A[j + 8];
        ull rcv = __shfl_xor_sync(0xffffffffu, snd, 16);
        A[j] = add2((m & 16) ? A[j + 8] : A[j], rcv);
    }
    #pragma unroll
    for (int j = 0; j < 4; j++) {
        ull snd = (m & 8) ? A[j] : A[j + 4];
        ull rcv = __shfl_xor_sync(0xffffffffu, snd, 8);
        A[j] = add2((m & 8) ? A[j + 4] : A[j], rcv);
    }
    #pragma unroll
    for (int j = 0; j < 2; j++) {
        ull snd = (m & 4) ? A[j] : A[j + 2];
        ull rcv = __shfl_xor_sync(0xffffffffu, snd, 4);
        A[j] = add2((m & 4) ? A[j + 2] : A[j], rcv);
    }
    {
        ull snd = (m & 2) ? A[0] : A[1];
        ull rcv = __shfl_xor_sync(0xffffffffu, snd, 2);
        A[0] = add2((m & 2) ? A[1] : A[0], rcv);
    }
    float lo = __uint_as_float((uint)A[0]);
    float hi = __uint_as_float((uint)(A[0] >> 32));
    float snd = (m & 1) ? lo : hi;
    float rcv = __shfl_xor_sync(0xffffffffu, snd, 1);
    return ((m & 1) ? hi : lo) + rcv;
}

__global__ __launch_bounds__(1024, 1) void fused_tail_kernel(
    const float* __restrict__ x,
    const float* __restrict__ Wd, const float* __restrict__ bd,
    const float* __restrict__ Wt, const float* __restrict__ bt,
    const float* __restrict__ Wa, const float* __restrict__ ba,
    const float* __restrict__ Wr, const float* __restrict__ br,
    const float* __restrict__ gamma, const float* __restrict__ beta,
    const float* __restrict__ dm,
    float* __restrict__ out)
{
    __shared__ __align__(16) float xs[32 * CW];
    __shared__ __align__(16) float ds[32 * CW];
    __shared__ __align__(16) float hs[32 * CW];
    __shared__ float Wt_s[128], bd_s[128], ba_s[128], br_s[128], g_s[128], be_s[128];
    __shared__ float redS[256], redQ[256];
    __shared__ float tau_s[8];
    __shared__ float musig[16];

    const int t = threadIdx.x;
    const int m = t & 31;                 // k-chunk (4 k's)
    const int warp = t >> 5;              // col-group (4 cols)
    const int colbase = warp * 4;
    const int k0 = m * 4;
    const int i0 = blockIdx.x * 8;
    const int col = colbase + ((m >> 3) & 3);
    const int row = m & 7;

    float4 wv[4];
    load_w(Wd, colbase, k0, wv);          // matvec-1 weights in flight early

    // ---- stage inputs: 1 elem/thread, coalesced ----
    {
        int r = t >> 7, k = t & 127;
        int o = IDX(k, r);
        xs[o] = x[(i0 + r) * DN + k];
        ds[o] = dm[(i0 + r) * DN + k];
    }
    if (t < 128)       { Wt_s[t] = Wt[t];             g_s[t] = gamma[t]; }
    else if (t < 256)  { bd_s[t - 128] = bd[t - 128]; be_s[t - 128] = beta[t - 128]; }
    else if (t < 384)  { ba_s[t - 256] = ba[t - 256]; }
    else if (t < 512)  { br_s[t - 384] = br[t - 384]; }
    __syncthreads();

    // ---- tau partials (warps 0-3; thread = k) ----
    if (t < 128) {
        int o = IDX(t, 0);
        float4 xa = *(const float4*)(xs + o);
        float4 xb = *(const float4*)(xs + o + 4);
        float wt = Wt_s[t];
        float pr[8] = { xa.x * wt, xa.y * wt, xa.z * wt, xa.w * wt,
                        xb.x * wt, xb.y * wt, xb.z * wt, xb.w * wt };
        #pragma unroll
        for (int r = 0; r < 8; r++) {
            float v = pr[r];
            #pragma unroll
            for (int o2 = 16; o2; o2 >>= 1) v += __shfl_xor_sync(0xffffffffu, v, o2);
            if (m == 0) redS[(t >> 5) * 8 + r] = v;
        }
    }
    __syncthreads();
    if (t < 8) {
        float z = redS[t] + redS[8 + t] + redS[16 + t] + redS[24 + t] + bt[0];
        float sp = fmaxf(z, 0.0f) + log1pf(expf(-fabsf(z)));
        tau_s[t] = fmaxf(sp, 0.01f) + 1.0f;
    }

    ull A[16];

    // ================= matvec 1: d_mean = dm @ Wd^T ; h_mean =================
    #pragma unroll
    for (int i = 0; i < 16; i++) A[i] = 0ull;
    mv_acc(ds + m * CW, wv, A);
    float s1 = butterfly32(A, m);
    __syncthreads();                       // tau_s ready (and redS free)
    {
        float hm = (s1 + bd_s[col]) / tau_s[row];
        hs[IDX(col, row)] = hm;
    }
    load_w(Wa, colbase, k0, wv);
    __syncthreads();                       // hs ready

    // ================= matvec 2: h = relu(hm @ Wa^T + ba) =================
    #pragma unroll
    for (int i = 0; i < 16; i++) A[i] = 0ull;
    mv_acc(hs + m * CW, wv, A);
    load_w(Wr, colbase, k0, wv);
    float s2 = butterfly32(A, m);
    float h = fmaxf(s2 + ba_s[col], 0.0f);

    // ================= matvec 3: y = h + x @ Wr^T + br =================
    #pragma unroll
    for (int i = 0; i < 16; i++) A[i] = 0ull;
    mv_acc(xs + m * CW, wv, A);
    float s3 = butterfly32(A, m);
    float y = h + s3 + br_s[col];

    // ---- LayerNorm ----
    float s = y, qq = y * y;
    s  += __shfl_xor_sync(0xffffffffu, s, 8);
    s  += __shfl_xor_sync(0xffffffffu, s, 16);
    qq += __shfl_xor_sync(0xffffffffu, qq, 8);
    qq += __shfl_xor_sync(0xffffffffu, qq, 16);
    if (m < 8) { redS[warp * 8 + m] = s; redQ[warp * 8 + m] = qq; }
    __syncthreads();
    if (t < 8) {
        float ss = 0.0f, qs = 0.0f;
        #pragma unroll
        for (int wp = 0; wp < 32; wp++) { ss += redS[wp * 8 + t]; qs += redQ[wp * 8 + t]; }
        float mu = ss * (1.0f / 128.0f);
        float var = qs * (1.0f / 128.0f) - mu * mu;
        musig[2 * t] = mu;
        musig[2 * t + 1] = rsqrtf(var + LN_EPS);
    }
    __syncthreads();
    out[(i0 + row) * HN + col] =
        (y - musig[2 * row]) * musig[2 * row + 1] * g_s[col] + be_s[col];
}

// ===========================================================================
extern "C" void kernel_launch(void* const* d_in, const int* in_sizes, int n_in,
                              void* d_out, int out_size)
{
    const float* x     = (const float*)d_in[0];
    const float* Wd    = (const float*)d_in[1];
    const float* bd    = (const float*)d_in[2];
    const float* Wt    = (const float*)d_in[3];
    const float* bt    = (const float*)d_in[4];
    const float* Wa    = (const float*)d_in[5];
    const float* ba    = (const float*)d_in[6];
    const float* Wr    = (const float*)d_in[7];
    const float* br    = (const float*)d_in[8];
    const float* gamma = (const float*)d_in[9];
    const float* beta  = (const float*)d_in[10];
    float* out = (float*)d_out;

    float* dm = nullptr;
    cudaGetSymbolAddress((void**)&dm, g_dm);

    col_absdiff_mean_kernel<<<DN, 512>>>(x, dm);
    fused_tail_kernel<<<BN / 8, 1024>>>(
        x, Wd, bd, Wt, bt, Wa, ba, Wr, br, gamma, beta, dm, out);
}

// round 6
// speedup vs baseline: 1.0135x; 1.0135x over previous
#include <cuda_runtime.h>
#include <math.h>

#define BN 1024
#define DN 128
#define HN 128
#define LN_EPS 1e-5f

__device__ float g_dm[BN * DN];

typedef unsigned long long ull;
typedef unsigned int uint;

// ===========================================================================
// order-preserving float <-> uint encode
// ===========================================================================
__device__ __forceinline__ uint encf(float f) {
    uint u = __float_as_uint(f);
    return u ^ ((u & 0x80000000u) ? 0xFFFFFFFFu : 0x80000000u);
}
__device__ __forceinline__ float decf(uint u) {
    u ^= (u & 0x80000000u) ? 0x80000000u : 0xFFFFFFFFu;
    return __uint_as_float(u);
}

// ===========================================================================
// K1: per-column mean |x_i - x_j| via hybrid bitonic sort. 128 blocks,
// 512 threads, 2 keys/thread. Named barriers scoped to dependent groups.
// ===========================================================================
__device__ __forceinline__ void g64(int t) {
    asm volatile("bar.sync %0, 64;"  :: "r"(1 + (t >> 6)) : "memory");
}
__device__ __forceinline__ void g128(int t) {
    asm volatile("bar.sync %0, 128;" :: "r"(9 + (t >> 7)) : "memory");
}
__device__ __forceinline__ void g256(int t) {
    asm volatile("bar.sync %0, 256;" :: "r"(13 + (t >> 8)) : "memory");
}

template<int K, int J>
__device__ __forceinline__ void sstage(uint* __restrict__ sv, int t) {
    int i = ((t & ~(J - 1)) << 1) | (t & (J - 1));
    int ixj = i | J;
    uint a = sv[i];
    uint b = sv[ixj];
    if ((a > b) == ((i & K) == 0)) { sv[i] = b; sv[ixj] = a; }
}

__device__ __forceinline__ void rtail(uint& r0, uint& r1, int p0, bool up) {
    uint lo = min(r0, r1), hi = max(r0, r1);
    r0 = up ? lo : hi;
    r1 = up ? hi : lo;
    #pragma unroll
    for (int j = 16; j > 0; j >>= 1) {
        bool km = (((p0 & j) == 0) == up);
        uint o0 = __shfl_xor_sync(0xffffffffu, r0, j);
        r0 = km ? min(r0, o0) : max(r0, o0);
        uint o1 = __shfl_xor_sync(0xffffffffu, r1, j);
        r1 = km ? min(r1, o1) : max(r1, o1);
    }
}

__global__ __launch_bounds__(512) void col_absdiff_mean_kernel(
    const float* __restrict__ x, float* __restrict__ dm)
{
    __shared__ uint  sv[BN];
    __shared__ float ps[BN];
    __shared__ float wsum[16];

    const int d = blockIdx.x;
    const int t = threadIdx.x;
    const int lane = t & 31;
    const int w = t >> 5;
    const int p0 = (w << 6) + lane;
    const int p1 = p0 + 32;

    const float f0 = x[p0 * DN + d];
    const float f1 = x[p1 * DN + d];
    const uint e0 = encf(f0);
    const uint e1 = encf(f1);
    uint r0 = e0, r1 = e1;

    // phase A: k = 2..64, registers/shfl only
    #pragma unroll
    for (int k = 2; k <= 64; k <<= 1) {
        #pragma unroll
        for (int j = k >> 1; j > 0; j >>= 1) {
            if (j == 32) {
                bool up = ((p0 & k) == 0);
                uint lo = min(r0, r1), hi = max(r0, r1);
                r0 = up ? lo : hi;
                r1 = up ? hi : lo;
            } else {
                bool up0 = ((p0 & k) == 0);
                bool km0 = (((p0 & j) == 0) == up0);
                uint o0 = __shfl_xor_sync(0xffffffffu, r0, j);
                r0 = km0 ? min(r0, o0) : max(r0, o0);
                bool up1 = ((p1 & k) == 0);
                bool km1 = (((p1 & j) == 0) == up1);
                uint o1 = __shfl_xor_sync(0xffffffffu, r1, j);
                r1 = km1 ? min(r1, o1) : max(r1, o1);
            }
        }
    }

    // phase B
    sv[p0] = r0; sv[p1] = r1;
    g64(t);
    sstage<128, 64>(sv, t);
    g64(t);
    r0 = sv[p0]; r1 = sv[p1];
    rtail(r0, r1, p0, (p0 & 128) == 0);

    sv[p0] = r0; sv[p1] = r1;
    g128(t);
    sstage<256, 128>(sv, t);
    g128(t);
    sstage<256, 64>(sv, t);
    g64(t);
    r0 = sv[p0]; r1 = sv[p1];
    rtail(r0, r1, p0, (p0 & 256) == 0);

    sv[p0] = r0; sv[p1] = r1;
    g256(t);
    sstage<512, 256>(sv, t);
    g256(t);
    sstage<512, 128>(sv, t);
    g128(t);
    sstage<512, 64>(sv, t);
    g64(t);
    r0 = sv[p0]; r1 = sv[p1];
    rtail(r0, r1, p0, (p0 & 512) == 0);

    sv[p0] = r0; sv[p1] = r1;
    __syncthreads();
    sstage<1024, 512>(sv, t);
    __syncthreads();
    sstage<1024, 256>(sv, t);
    g256(t);
    sstage<1024, 128>(sv, t);
    g128(t);
    sstage<1024, 64>(sv, t);
    g64(t);
    r0 = sv[p0]; r1 = sv[p1];
    rtail(r0, r1, p0, true);

    // sorted keys + prefix sums
    sv[p0] = r0;
    sv[p1] = r1;
    float v0 = decf(r0);
    float v1 = decf(r1);

    float s0 = v0;
    #pragma unroll
    for (int o = 1; o < 32; o <<= 1) {
        float n = __shfl_up_sync(0xffffffffu, s0, o);
        if (lane >= o) s0 += n;
    }
    float T0 = __shfl_sync(0xffffffffu, s0, 31);
    float s1 = v1;
    #pragma unroll
    for (int o = 1; o < 32; o <<= 1) {
        float n = __shfl_up_sync(0xffffffffu, s1, o);
        if (lane >= o) s1 += n;
    }
    float T1 = __shfl_sync(0xffffffffu, s1, 31);
    if (lane == 0) wsum[w] = T0 + T1;
    __syncthreads();
    if (t < 16) {
        float v = wsum[t];
        #pragma unroll
        for (int o = 1; o < 16; o <<= 1) {
            float n = __shfl_up_sync(0x0000ffffu, v, o);
            if (t >= o) v += n;
        }
        wsum[t] = v;
    }
    __syncthreads();
    const float S = wsum[15];
    const float wexcl = (w == 0) ? 0.0f : wsum[w - 1];
    ps[p0] = wexcl + s0;
    ps[p1] = wexcl + T0 + s1;
    __syncthreads();

    // binary-search ranks; closed-form write
    {
        int q = 0;
        #pragma unroll
        for (int st = 512; st > 0; st >>= 1) {
            int nq = q + st;
            if (sv[nq - 1] < e0) q = nq;
        }
        float o = f0 * (float)(2 * (q + 1) - BN) + S - 2.0f * ps[q];
        dm[p0 * DN + d] = o * (1.0f / (float)BN);
    }
    {
        int q = 0;
        #pragma unroll
        for (int st = 512; st > 0; st >>= 1) {
            int nq = q + st;
            if (sv[nq - 1] < e1) q = nq;
        }
        float o = f1 * (float)(2 * (q + 1) - BN) + S - 2.0f * ps[q];
        dm[p1 * DN + d] = o * (1.0f / (float)BN);
    }
}

// ===========================================================================
// K3: fused tail. 256 blocks x 4 rows, 512 threads, 2 CTAs/SM.
// Halfwarp = col-group of 4 cols; lane m = lane&15 = k-chunk (8 k's).
// Weights direct LDG.128 (L2-resident).  Accumulators: 8 ull (4c x 4r / 2).
// Butterfly over 16 lanes, payload 8 ull -> 1 float (col=m>>2, row=m&3).
// ===========================================================================
__device__ __forceinline__ ull fma2(ull a, ull b, ull c) {
    ull d;
    asm("fma.rn.f32x2 %0, %1, %2, %3;" : "=l"(d) : "l"(a), "l"(b), "l"(c));
    return d;
}
__device__ __forceinline__ ull add2(ull a, ull b) {
    ull d;
    asm("add.rn.f32x2 %0, %1, %2;" : "=l"(d) : "l"(a), "l"(b));
    return d;
}
__device__ __forceinline__ ull dup2(float w) {
    ull d;
    asm("mov.b64 %0, {%1, %1};" : "=l"(d) : "r"(__float_as_uint(w)));
    return d;
}

#define CW 36   /* floats per 8-k chunk: 8k*4r = 32 data + 4 pad */
#define IDX(k, r) ((((k) >> 3) * CW) + (((k) & 7) << 2) + (r))

__device__ __forceinline__ void load_w(const float* __restrict__ W,
                                       int colbase, int k0, float4 wv[8])
{
    #pragma unroll
    for (int c = 0; c < 4; c++) {
        const float4* p = (const float4*)(W + (colbase + c) * DN + k0);
        wv[c * 2]     = p[0];
        wv[c * 2 + 1] = p[1];
    }
}

__device__ __forceinline__ void mv_acc(const float* __restrict__ ip,
                                       const float4 wv[8], ull A[8])
{
    #pragma unroll
    for (int kl = 0; kl < 8; kl++) {
        ulonglong2 q = *(const ulonglong2*)(ip + kl * 4);   // rows 0-3
        #pragma unroll
        for (int c = 0; c < 4; c++) {
            ull w2 = dup2(((const float*)&wv[c * 2 + (kl >> 2)])[kl & 3]);
            A[c * 2 + 0] = fma2(q.x, w2, A[c * 2 + 0]);
            A[c * 2 + 1] = fma2(q.y, w2, A[c * 2 + 1]);
        }
    }
}

// 4-stage recursive-halving butterfly over 16 lanes, payload 8 ull.
// lane m ends with scalar for (col = m>>2 of group, row = m&3).
__device__ __forceinline__ float butterfly16(ull A[8], int m)
{
    #pragma unroll
    for (int j = 0; j < 4; j++) {
        ull snd = (m & 8) ? A[j] : A[j + 4];
        ull rcv = __shfl_xor_sync(0xffffffffu, snd, 8);
        A[j] = add2((m & 8) ? A[j + 4] : A[j], rcv);
    }
    #pragma unroll
    for (int j = 0; j < 2; j++) {
        ull snd = (m & 4) ? A[j] : A[j + 2];
        ull rcv = __shfl_xor_sync(0xffffffffu, snd, 4);
        A[j] = add2((m & 4) ? A[j + 2] : A[j], rcv);
    }
    {
        ull snd = (m & 2) ? A[0] : A[1];
        ull rcv = __shfl_xor_sync(0xffffffffu, snd, 2);
        A[0] = add2((m & 2) ? A[1] : A[0], rcv);
    }
    float lo = __uint_as_float((uint)A[0]);
    float hi = __uint_as_float((uint)(A[0] >> 32));
    float snd = (m & 1) ? lo : hi;
    float rcv = __shfl_xor_sync(0xffffffffu, snd, 1);
    return ((m & 1) ? hi : lo) + rcv;
}

__global__ __launch_bounds__(512, 2) void fused_tail_kernel(
    const float* __restrict__ x,
    const float* __restrict__ Wd, const float* __restrict__ bd,
    const float* __restrict__ Wt, const float* __restrict__ bt,
    const float* __restrict__ Wa, const float* __restrict__ ba,
    const float* __restrict__ Wr, const float* __restrict__ br,
    const float* __restrict__ gamma, const float* __restrict__ beta,
    const float* __restrict__ dm,
    float* __restrict__ out)
{
    __shared__ __align__(16) float xs[16 * CW];
    __shared__ __align__(16) float ds[16 * CW];
    __shared__ __align__(16) float hs[16 * CW];
    __shared__ float Wt_s[128], bd_s[128], ba_s[128], br_s[128], g_s[128], be_s[128];
    __shared__ float redS[64], redQ[64];
    __shared__ float tau_s[4];
    __shared__ float musig[8];

    const int t = threadIdx.x;
    const int lane = t & 31;
    const int m = lane & 15;              // k-chunk (8 k's)
    const int colbase = (t >> 4) * 4;     // halfwarp -> col group
    const int k0 = m * 8;
    const int i0 = blockIdx.x * 4;
    const int col = colbase + (m >> 2);
    const int row = m & 3;

    float4 wv[8];
    load_w(Wd, colbase, k0, wv);          // matvec-1 weights in flight early

    // stage inputs: 1 elem/thread, coalesced (512 = 4 rows x 128 k)
    {
        int r = t >> 7, k = t & 127;
        int o = IDX(k, r);
        xs[o] = x[(i0 + r) * DN + k];
        ds[o] = dm[(i0 + r) * DN + k];
    }
    if (t < 128)       { Wt_s[t] = Wt[t];             g_s[t] = gamma[t]; }
    else if (t < 256)  { bd_s[t - 128] = bd[t - 128]; be_s[t - 128] = beta[t - 128]; }
    else if (t < 384)  { ba_s[t - 256] = ba[t - 256]; }
    else               { br_s[t - 384] = br[t - 384]; }
    __syncthreads();

    // tau partials (warps 0-3; thread = k)
    if (t < 128) {
        int o = IDX(t, 0);
        float4 xa = *(const float4*)(xs + o);
        float wt = Wt_s[t];
        float pr[4] = { xa.x * wt, xa.y * wt, xa.z * wt, xa.w * wt };
        #pragma unroll
        for (int r = 0; r < 4; r++) {
            float v = pr[r];
            #pragma unroll
            for (int o2 = 16; o2; o2 >>= 1) v += __shfl_xor_sync(0xffffffffu, v, o2);
            if (lane == 0) redS[(t >> 5) * 4 + r] = v;
        }
    }
    __syncthreads();
    if (t < 4) {
        float z = redS[t] + redS[4 + t] + redS[8 + t] + redS[12 + t] + bt[0];
        float sp = fmaxf(z, 0.0f) + log1pf(expf(-fabsf(z)));
        tau_s[t] = fmaxf(sp, 0.01f) + 1.0f;
    }

    ull A[8];

    // ===== matvec 1: d_mean = dm @ Wd^T ; h_mean = (.+bd)/tau =====
    #pragma unroll
    for (int i = 0; i < 8; i++) A[i] = 0ull;
    mv_acc(ds + m * CW, wv, A);
    float s1 = butterfly16(A, m);
    __syncthreads();                       // tau_s ready
    hs[IDX(col, row)] = (s1 + bd_s[col]) / tau_s[row];
    load_w(Wa, colbase, k0, wv);
    __syncthreads();                       // hs ready

    // ===== matvec 2: h = relu(hm @ Wa^T + ba) =====
    #pragma unroll
    for (int i = 0; i < 8; i++) A[i] = 0ull;
    mv_acc(hs + m * CW, wv, A);
    load_w(Wr, colbase, k0, wv);
    float s2 = butterfly16(A, m);
    float h = fmaxf(s2 + ba_s[col], 0.0f);

    // ===== matvec 3: y = h + x @ Wr^T + br  (xs untouched; no sync) =====
    #pragma unroll
    for (int i = 0; i < 8; i++) A[i] = 0ull;
    mv_acc(xs + m * CW, wv, A);
    float s3 = butterfly16(A, m);
    float y = h + s3 + br_s[col];

    // ===== LayerNorm over 128 cols per row =====
    float s = y, qq = y * y;
    #pragma unroll
    for (int mk = 4; mk <= 16; mk <<= 1) {
        s  += __shfl_xor_sync(0xffffffffu, s, mk);
        qq += __shfl_xor_sync(0xffffffffu, qq, mk);
    }
    if (lane < 4) { redS[(t >> 5) * 4 + lane] = s; redQ[(t >> 5) * 4 + lane] = qq; }
    __syncthreads();
    if (t < 4) {
        float ss = 0.0f, qs = 0.0f;
        #pragma unroll
        for (int wp = 0; wp < 16; wp++) { ss += redS[wp * 4 + t]; qs += redQ[wp * 4 + t]; }
        float mu = ss * (1.0f / 128.0f);
        float var = qs * (1.0f / 128.0f) - mu * mu;
        musig[2 * t] = mu;
        musig[2 * t + 1] = rsqrtf(var + LN_EPS);
    }
    __syncthreads();
    out[(i0 + row) * HN + col] =
        (y - musig[2 * row]) * musig[2 * row + 1] * g_s[col] + be_s[col];
}

// ===========================================================================
extern "C" void kernel_launch(void* const* d_in, const int* in_sizes, int n_in,
                              void* d_out, int out_size)
{
    const float* x     = (const float*)d_in[0];
    const float* Wd    = (const float*)d_in[1];
    const float* bd    = (const float*)d_in[2];
    const float* Wt    = (const float*)d_in[3];
    const float* bt    = (const float*)d_in[4];
    const float* Wa    = (const float*)d_in[5];
    const float* ba    = (const float*)d_in[6];
    const float* Wr    = (const float*)d_in[7];
    const float* br    = (const float*)d_in[8];
    const float* gamma = (const float*)d_in[9];
    const float* beta  = (const float*)d_in[10];
    float* out = (float*)d_out;

    float* dm = nullptr;
    cudaGetSymbolAddress((void**)&dm, g_dm);

    col_absdiff_mean_kernel<<<DN, 512>>>(x, dm);
    fused_tail_kernel<<<BN / 4, 512>>>(
        x, Wd, bd, Wt, bt, Wa, ba, Wr, br, gamma, beta, dm, out);
}

// round 8
// speedup vs baseline: 1.1366x; 1.1214x over previous
#include <cuda_runtime.h>
#include <math.h>

#define BN 1024
#define DN 128
#define HN 128
#define LN_EPS 1e-5f

__device__ float g_dm[BN * DN];

typedef unsigned long long ull;
typedef unsigned int uint;

// ===========================================================================
// order-preserving float <-> uint encode
// ===========================================================================
__device__ __forceinline__ uint encf(float f) {
    uint u = __float_as_uint(f);
    return u ^ ((u & 0x80000000u) ? 0xFFFFFFFFu : 0x80000000u);
}
__device__ __forceinline__ float decf(uint u) {
    u ^= (u & 0x80000000u) ? 0x80000000u : 0xFFFFFFFFu;
    return __uint_as_float(u);
}

// ===========================================================================
// K1: per-column mean |x_i - x_j| via hybrid bitonic sort. 128 blocks,
// 512 threads, 2 keys/thread. Named barriers scoped to dependent groups.
// ===========================================================================
__device__ __forceinline__ void g64(int t) {
    asm volatile("bar.sync %0, 64;"  :: "r"(1 + (t >> 6)) : "memory");
}
__device__ __forceinline__ void g128(int t) {
    asm volatile("bar.sync %0, 128;" :: "r"(9 + (t >> 7)) : "memory");
}
__device__ __forceinline__ void g256(int t) {
    asm volatile("bar.sync %0, 256;" :: "r"(13 + (t >> 8)) : "memory");
}

template<int K, int J>
__device__ __forceinline__ void sstage(uint* __restrict__ sv, int t) {
    int i = ((t & ~(J - 1)) << 1) | (t & (J - 1));
    int ixj = i | J;
    uint a = sv[i];
    uint b = sv[ixj];
    if ((a > b) == ((i & K) == 0)) { sv[i] = b; sv[ixj] = a; }
}

__device__ __forceinline__ void rtail(uint& r0, uint& r1, int p0, bool up) {
    uint lo = min(r0, r1), hi = max(r0, r1);
    r0 = up ? lo : hi;
    r1 = up ? hi : lo;
    #pragma unroll
    for (int j = 16; j > 0; j >>= 1) {
        bool km = (((p0 & j) == 0) == up);
        uint o0 = __shfl_xor_sync(0xffffffffu, r0, j);
        r0 = km ? min(r0, o0) : max(r0, o0);
        uint o1 = __shfl_xor_sync(0xffffffffu, r1, j);
        r1 = km ? min(r1, o1) : max(r1, o1);
    }
}

__global__ __launch_bounds__(512) void col_absdiff_mean_kernel(
    const float* __restrict__ x, float* __restrict__ dm)
{
    __shared__ uint  sv[BN];
    __shared__ float ps[BN];
    __shared__ float wsum[16];

    const int d = blockIdx.x;
    const int t = threadIdx.x;
    const int lane = t & 31;
    const int w = t >> 5;
    const int p0 = (w << 6) + lane;
    const int p1 = p0 + 32;

    const float f0 = x[p0 * DN + d];
    const float f1 = x[p1 * DN + d];
    const uint e0 = encf(f0);
    const uint e1 = encf(f1);
    uint r0 = e0, r1 = e1;

    // phase A: k = 2..64, registers/shfl only
    #pragma unroll
    for (int k = 2; k <= 64; k <<= 1) {
        #pragma unroll
        for (int j = k >> 1; j > 0; j >>= 1) {
            if (j == 32) {
                bool up = ((p0 & k) == 0);
                uint lo = min(r0, r1), hi = max(r0, r1);
                r0 = up ? lo : hi;
                r1 = up ? hi : lo;
            } else {
                bool up0 = ((p0 & k) == 0);
                bool km0 = (((p0 & j) == 0) == up0);
                uint o0 = __shfl_xor_sync(0xffffffffu, r0, j);
                r0 = km0 ? min(r0, o0) : max(r0, o0);
                bool up1 = ((p1 & k) == 0);
                bool km1 = (((p1 & j) == 0) == up1);
                uint o1 = __shfl_xor_sync(0xffffffffu, r1, j);
                r1 = km1 ? min(r1, o1) : max(r1, o1);
            }
        }
    }

    // phase B
    sv[p0] = r0; sv[p1] = r1;
    g64(t);
    sstage<128, 64>(sv, t);
    g64(t);
    r0 = sv[p0]; r1 = sv[p1];
    rtail(r0, r1, p0, (p0 & 128) == 0);

    sv[p0] = r0; sv[p1] = r1;
    g128(t);
    sstage<256, 128>(sv, t);
    g128(t);
    sstage<256, 64>(sv, t);
    g64(t);
    r0 = sv[p0]; r1 = sv[p1];
    rtail(r0, r1, p0, (p0 & 256) == 0);

    sv[p0] = r0; sv[p1] = r1;
    g256(t);
    sstage<512, 256>(sv, t);
    g256(t);
    sstage<512, 128>(sv, t);
    g128(t);
    sstage<512, 64>(sv, t);
    g64(t);
    r0 = sv[p0]; r1 = sv[p1];
    rtail(r0, r1, p0, (p0 & 512) == 0);

    sv[p0] = r0; sv[p1] = r1;
    __syncthreads();
    sstage<1024, 512>(sv, t);
    __syncthreads();
    sstage<1024, 256>(sv, t);
    g256(t);
    sstage<1024, 128>(sv, t);
    g128(t);
    sstage<1024, 64>(sv, t);
    g64(t);
    r0 = sv[p0]; r1 = sv[p1];
    rtail(r0, r1, p0, true);

    // sorted keys + prefix sums
    sv[p0] = r0;
    sv[p1] = r1;
    float v0 = decf(r0);
    float v1 = decf(r1);

    float s0 = v0;
    #pragma unroll
    for (int o = 1; o < 32; o <<= 1) {
        float n = __shfl_up_sync(0xffffffffu, s0, o);
        if (lane >= o) s0 += n;
    }
    float T0 = __shfl_sync(0xffffffffu, s0, 31);
    float s1 = v1;
    #pragma unroll
    for (int o = 1; o < 32; o <<= 1) {
        float n = __shfl_up_sync(0xffffffffu, s1, o);
        if (lane >= o) s1 += n;
    }
    float T1 = __shfl_sync(0xffffffffu, s1, 31);
    if (lane == 0) wsum[w] = T0 + T1;
    __syncthreads();
    if (t < 16) {
        float v = wsum[t];
        #pragma unroll
        for (int o = 1; o < 16; o <<= 1) {
            float n = __shfl_up_sync(0x0000ffffu, v, o);
            if (t >= o) v += n;
        }
        wsum[t] = v;
    }
    __syncthreads();
    const float S = wsum[15];
    const float wexcl = (w == 0) ? 0.0f : wsum[w - 1];
    ps[p0] = wexcl + s0;
    ps[p1] = wexcl + T0 + s1;
    __syncthreads();

    // binary-search ranks; closed-form write
    {
        int q = 0;
        #pragma unroll
        for (int st = 512; st > 0; st >>= 1) {
            int nq = q + st;
            if (sv[nq - 1] < e0) q = nq;
        }
        float o = f0 * (float)(2 * (q + 1) - BN) + S - 2.0f * ps[q];
        dm[p0 * DN + d] = o * (1.0f / (float)BN);
    }
    {
        int q = 0;
        #pragma unroll
        for (int st = 512; st > 0; st >>= 1) {
            int nq = q + st;
            if (sv[nq - 1] < e1) q = nq;
        }
        float o = f1 * (float)(2 * (q + 1) - BN) + S - 2.0f * ps[q];
        dm[p1 * DN + d] = o * (1.0f / (float)BN);
    }
}

// ===========================================================================
// K3: fused tail (R4 shape + mv1/mv3 interleave).
// 128 blocks x 8 rows, 512 threads. Half-warp = col-group of 4 cols;
// m = lane&15 = k-chunk of 8 k's. Weights direct LDG.128 in k-halves.
// Phase 1: mv1 (dm@Wd) and mv3 (x@Wr) interleaved; dual butterfly.
// Phase 2: mv2 (hm@Wa).
// ===========================================================================
__device__ __forceinline__ ull fma2(ull a, ull b, ull c) {
    ull d;
    asm("fma.rn.f32x2 %0, %1, %2, %3;" : "=l"(d) : "l"(a), "l"(b), "l"(c));
    return d;
}
__device__ __forceinline__ ull add2(ull a, ull b) {
    ull d;
    asm("add.rn.f32x2 %0, %1, %2;" : "=l"(d) : "l"(a), "l"(b));
    return d;
}
__device__ __forceinline__ ull dup2(float w) {
    ull d;
    asm("mov.b64 %0, {%1, %1};" : "=l"(d) : "r"(__float_as_uint(w)));
    return d;
}

#define CHW 68   /* floats per 8-k chunk: 8k*8r = 64 data + 4 pad */
#define IDX(k, r) ((((k) >> 3) * CHW) + (((k) & 7) << 3) + (r))

// load 4 cols x 4 k's (half of a k-chunk) : wv[c] = W[colbase+c][k0..k0+3]
__device__ __forceinline__ void load_w4(const float* __restrict__ W,
                                        int colbase, int k0, float4 wv[4])
{
    #pragma unroll
    for (int c = 0; c < 4; c++)
        wv[c] = *(const float4*)(W + (colbase + c) * DN + k0);
}

// accumulate 4 k's (kl offset base kb) from input ip into A[16]
__device__ __forceinline__ void mv_acc4(const float* __restrict__ ip, int kb,
                                        const float4 wv[4], ull A[16])
{
    #pragma unroll
    for (int kl = 0; kl < 4; kl++) {
        ulonglong2 q0 = *(const ulonglong2*)(ip + (kb + kl) * 8);
        ulonglong2 q1 = *(const ulonglong2*)(ip + (kb + kl) * 8 + 4);
        #pragma unroll
        for (int c = 0; c < 4; c++) {
            ull w2 = dup2(((const float*)&wv[c])[kl]);
            A[c * 4 + 0] = fma2(q0.x, w2, A[c * 4 + 0]);
            A[c * 4 + 1] = fma2(q0.y, w2, A[c * 4 + 1]);
            A[c * 4 + 2] = fma2(q1.x, w2, A[c * 4 + 2]);
            A[c * 4 + 3] = fma2(q1.y, w2, A[c * 4 + 3]);
        }
    }
}

// dual butterfly over 16 lanes, payloads A and B reduced simultaneously.
// lane m ends with packed row-pair scalars in A[0] and B[0]
// for (col = m>>2 of group, rows 2*(m&3), 2*(m&3)+1).
__device__ __forceinline__ void butterfly16x2(ull A[16], ull B[16], int m)
{
    #pragma unroll
    for (int j = 0; j < 8; j++) {
        ull sa = (m & 8) ? A[j] : A[j + 8];
        ull sb = (m & 8) ? B[j] : B[j + 8];
        ull ca = __shfl_xor_sync(0xffffffffu, sa, 8);
        ull cb = __shfl_xor_sync(0xffffffffu, sb, 8);
        A[j] = add2((m & 8) ? A[j + 8] : A[j], ca);
        B[j] = add2((m & 8) ? B[j + 8] : B[j], cb);
    }
    #pragma unroll
    for (int j = 0; j < 4; j++) {
        ull sa = (m & 4) ? A[j] : A[j + 4];
        ull sb = (m & 4) ? B[j] : B[j + 4];
        ull ca = __shfl_xor_sync(0xffffffffu, sa, 4);
        ull cb = __shfl_xor_sync(0xffffffffu, sb, 4);
        A[j] = add2((m & 4) ? A[j + 4] : A[j], ca);
        B[j] = add2((m & 4) ? B[j + 4] : B[j], cb);
    }
    #pragma unroll
    for (int j = 0; j < 2; j++) {
        ull sa = (m & 2) ? A[j] : A[j + 2];
        ull sb = (m & 2) ? B[j] : B[j + 2];
        ull ca = __shfl_xor_sync(0xffffffffu, sa, 2);
        ull cb = __shfl_xor_sync(0xffffffffu, sb, 2);
        A[j] = add2((m & 2) ? A[j + 2] : A[j], ca);
        B[j] = add2((m & 2) ? B[j + 2] : B[j], cb);
    }
    {
        ull sa = (m & 1) ? A[0] : A[1];
        ull sb = (m & 1) ? B[0] : B[1];
        ull ca = __shfl_xor_sync(0xffffffffu, sa, 1);
        ull cb = __shfl_xor_sync(0xffffffffu, sb, 1);
        A[0] = add2((m & 1) ? A[1] : A[0], ca);
        B[0] = add2((m & 1) ? B[1] : B[0], cb);
    }
}

__global__ __launch_bounds__(512) void fused_tail_kernel(
    const float* __restrict__ x,
    const float* __restrict__ Wd, const float* __restrict__ bd,
    const float* __restrict__ Wt, const float* __restrict__ bt,
    const float* __restrict__ Wa, const float* __restrict__ ba,
    const float* __restrict__ Wr, const float* __restrict__ br,
    const float* __restrict__ gamma, const float* __restrict__ beta,
    const float* __restrict__ dm,
    float* __restrict__ out)
{
    __shared__ __align__(16) float xs[16 * CHW];
    __shared__ __align__(16) float ds[16 * CHW];
    __shared__ __align__(16) float hs[16 * CHW];
    __shared__ float Wt_s[128], bd_s[128], ba_s[128], br_s[128], g_s[128], be_s[128];
    __shared__ float redS[128], redQ[128];
    __shared__ float rtau_s[8];
    __shared__ float musig[16];

    const int t = threadIdx.x;
    const int lane = t & 31;
    const int m = lane & 15;
    const int colbase = (t >> 4) * 4;
    const int k0 = m * 8;
    const int i0 = blockIdx.x * 8;
    const int col = colbase + (m >> 2);
    const int r0 = 2 * (m & 3);

    float4 wd[4], wr[4];
    load_w4(Wd, colbase, k0, wd);          // lo halves in flight early
    load_w4(Wr, colbase, k0, wr);

    // ---- stage inputs ----
    #pragma unroll
    for (int it = 0; it < 2; it++) {
        int e = t + it * 512;
        int r = e >> 7, k = e & 127;
        int o = IDX(k, r);
        xs[o] = x[(i0 + r) * DN + k];
        ds[o] = dm[(i0 + r) * DN + k];
    }
    if (t < 128)       { Wt_s[t] = Wt[t];             g_s[t] = gamma[t]; }
    else if (t < 256)  { bd_s[t - 128] = bd[t - 128]; be_s[t - 128] = beta[t - 128]; }
    else if (t < 384)  { ba_s[t - 256] = ba[t - 256]; }
    else               { br_s[t - 384] = br[t - 384]; }
    __syncthreads();

    // ---- tau partials (threads 0..127 = 128 k's) ----
    if (t < 128) {
        int o = IDX(t, 0);
        float4 xa = *(const float4*)(xs + o);
        float4 xb = *(const float4*)(xs + o + 4);
        float wt = Wt_s[t];
        float pr[8] = { xa.x * wt, xa.y * wt, xa.z * wt, xa.w * wt,
                        xb.x * wt, xb.y * wt, xb.z * wt, xb.w * wt };
        #pragma unroll
        for (int r = 0; r < 8; r++) {
            float v = pr[r];
            #pragma unroll
            for (int o2 = 16; o2; o2 >>= 1) v += __shfl_xor_sync(0xffffffffu, v, o2);
            if (lane == 0) redS[(t >> 5) * 8 + r] = v;
        }
    }
    __syncthreads();
    if (t < 8) {
        float z = redS[t] + redS[8 + t] + redS[16 + t] + redS[24 + t] + bt[0];
        float sp = fmaxf(z, 0.0f) + log1pf(expf(-fabsf(z)));
        rtau_s[t] = 1.0f / (fmaxf(sp, 0.01f) + 1.0f);
    }

    ull A1[16], A3[16];
    #pragma unroll
    for (int i = 0; i < 16; i++) { A1[i] = 0ull; A3[i] = 0ull; }

    const float* dsp = ds + m * CHW;
    const float* xsp = xs + m * CHW;

    // ===== phase 1: mv1 (dm@Wd) and mv3 (x@Wr) interleaved =====
    mv_acc4(dsp, 0, wd, A1);
    mv_acc4(xsp, 0, wr, A3);
    load_w4(Wd, colbase, k0 + 4, wd);      // hi halves
    load_w4(Wr, colbase, k0 + 4, wr);
    mv_acc4(dsp, 4, wd, A1);
    mv_acc4(xsp, 4, wr, A3);

    butterfly16x2(A1, A3, m);
    float s1a = __uint_as_float((uint)A1[0]);
    float s1b = __uint_as_float((uint)(A1[0] >> 32));
    float s3a = __uint_as_float((uint)A3[0]);
    float s3b = __uint_as_float((uint)(A3[0] >> 32));

    __syncthreads();                        // rtau ready
    {
        float bdv = bd_s[col];
        float hm0 = (s1a + bdv) * rtau_s[r0];
        float hm1 = (s1b + bdv) * rtau_s[r0 + 1];
        *(float2*)(hs + IDX(col, r0)) = make_float2(hm0, hm1);
    }
    // prefetch Wa (accumulator regs dead now)
    float4 wa[4], wa2[4];
    load_w4(Wa, colbase, k0, wa);
    load_w4(Wa, colbase, k0 + 4, wa2);
    __syncthreads();                        // hs ready

    // ===== phase 2: mv2 (hm@Wa) =====
    #pragma unroll
    for (int i = 0; i < 16; i++) A1[i] = 0ull;
    const float* hsp = hs + m * CHW;
    mv_acc4(hsp, 0, wa, A1);
    mv_acc4(hsp, 4, wa2, A1);

    // single butterfly
    #pragma unroll
    for (int j = 0; j < 8; j++) {
        ull s = (m & 8) ? A1[j] : A1[j + 8];
        ull c = __shfl_xor_sync(0xffffffffu, s, 8);
        A1[j] = add2((m & 8) ? A1[j + 8] : A1[j], c);
    }
    #pragma unroll
    for (int j = 0; j < 4; j++) {
        ull s = (m & 4) ? A1[j] : A1[j + 4];
        ull c = __shfl_xor_sync(0xffffffffu, s, 4);
        A1[j] = add2((m & 4) ? A1[j + 4] : A1[j], c);
    }
    #pragma unroll
    for (int j = 0; j < 2; j++) {
        ull s = (m & 2) ? A1[j] : A1[j + 2];
        ull c = __shfl_xor_sync(0xffffffffu, s, 2);
        A1[j] = add2((m & 2) ? A1[j + 2] : A1[j], c);
    }
    {
        ull s = (m & 1) ? A1[0] : A1[1];
        ull c = __shfl_xor_sync(0xffffffffu, s, 1);
        A1[0] = add2((m & 1) ? A1[1] : A1[0], c);
    }
    float s2a = __uint_as_float((uint)A1[0]);
    float s2b = __uint_as_float((uint)(A1[0] >> 32));

    float bav = ba_s[col], brv = br_s[col];
    float y0 = fmaxf(s2a + bav, 0.0f) + s3a + brv;
    float y1 = fmaxf(s2b + bav, 0.0f) + s3b + brv;

    // ---- LayerNorm reductions (rows r0, r0+1 per lane; 128 cols) ----
    float sa = y0, qa = y0 * y0, sb2 = y1, qb2 = y1 * y1;
    #pragma unroll
    for (int mk = 4; mk <= 16; mk <<= 1) {
        sa  += __shfl_xor_sync(0xffffffffu, sa, mk);
        qa  += __shfl_xor_sync(0xffffffffu, qa, mk);
        sb2 += __shfl_xor_sync(0xffffffffu, sb2, mk);
        qb2 += __shfl_xor_sync(0xffffffffu, qb2, mk);
    }
    if (lane < 4) {
        int wp = t >> 5;
        redS[wp * 8 + r0] = sa;      redQ[wp * 8 + r0] = qa;
        redS[wp * 8 + r0 + 1] = sb2; redQ[wp * 8 + r0 + 1] = qb2;
    }
    __syncthreads();
    if (t < 8) {
        float ss = 0.0f, qs = 0.0f;
        #pragma unroll
        for (int wp = 0; wp < 16; wp++) { ss += redS[wp * 8 + t]; qs += redQ[wp * 8 + t]; }
        float mu = ss * (1.0f / 128.0f);
        float var = qs * (1.0f / 128.0f) - mu * mu;
        musig[2 * t] = mu;
        musig[2 * t + 1] = rsqrtf(var + LN_EPS);
    }
    __syncthreads();
    float gv = g_s[col], bv = be_s[col];
    out[(i0 + r0) * HN + col]     = (y0 - musig[2 * r0]) * musig[2 * r0 + 1] * gv + bv;
    out[(i0 + r0 + 1) * HN + col] = (y1 - musig[2 * r0 + 2]) * musig[2 * r0 + 3] * gv + bv;
}

// ===========================================================================
extern "C" void kernel_launch(void* const* d_in, const int* in_sizes, int n_in,
                              void* d_out, int out_size)
{
    const float* x     = (const float*)d_in[0];
    const float* Wd    = (const float*)d_in[1];
    const float* bd    = (const float*)d_in[2];
    const float* Wt    = (const float*)d_in[3];
    const float* bt    = (const float*)d_in[4];
    const float* Wa    = (const float*)d_in[5];
    const float* ba    = (const float*)d_in[6];
    const float* Wr    = (const float*)d_in[7];
    const float* br    = (const float*)d_in[8];
    const float* gamma = (const float*)d_in[9];
    const float* beta  = (const float*)d_in[10];
    float* out = (float*)d_out;

    float* dm = nullptr;
    cudaGetSymbolAddress((void**)&dm, g_dm);

    col_absdiff_mean_kernel<<<DN, 512>>>(x, dm);
    fused_tail_kernel<<<BN / 8, 512>>>(
        x, Wd, bd, Wt, bt, Wa, ba, Wr, br, gamma, beta, dm, out);
}